// round 8
// baseline (speedup 1.0000x reference)
#include <cuda_runtime.h>
#include <math_constants.h>

#define Bsz 2048
#define Dd 16
#define Ff 512
#define LOG2E_F 1.4426950408889634f
#define LN2_F 0.6931471805599453f
#define LOG2PI_F 1.8378770664093453f

#define NRECON 64            // recon blocks at the front of k_main's grid
#define NPAIR 256            // pairwise blocks (8 rows each)
#define NGRID (NRECON + NPAIR)

typedef unsigned long long ull;

// Coefficient store: segment s = dp*3 + type (dp=dim-pair 0..7, type a/b/c),
// each segment is float2[2048] over j: float2[j] = {coef_{2dp}[j], coef_{2dp+1}[j]}
__device__ float g_pk2f[24 * 2048 * 2];   // 393 KB
__device__ float g_arr0[Bsz];             // log q(z|x) - log p(z)
__device__ float g_lqz[Bsz];              // lg2(srow)
__device__ float g_lqzp[Bsz];             // sum_d lg2(s_d)
__device__ float g_part[NRECON];          // recon partials
__device__ unsigned g_count;              // last-block-done counter

__device__ __forceinline__ float ex2f(float x) {
    float y; asm("ex2.approx.ftz.f32 %0, %1;" : "=f"(y) : "f"(x)); return y;
}
__device__ __forceinline__ float lg2f_(float x) {
    float y; asm("lg2.approx.f32 %0, %1;" : "=f"(y) : "f"(x)); return y;
}
__device__ __forceinline__ ull fma2_(ull a, ull b, ull c) {
    ull d; asm("fma.rn.f32x2 %0, %1, %2, %3;" : "=l"(d) : "l"(a), "l"(b), "l"(c)); return d;
}
__device__ __forceinline__ ull add2_(ull a, ull b) {
    ull d; asm("add.rn.f32x2 %0, %1, %2;" : "=l"(d) : "l"(a), "l"(b)); return d;
}
__device__ __forceinline__ void unpk(ull v, float& lo, float& hi) {
    asm("mov.b64 {%0, %1}, %2;" : "=f"(lo), "=f"(hi) : "l"(v));
}
__device__ __forceinline__ ull pk2(float lo, float hi) {
    ull v; asm("mov.b64 %0, {%1, %2};" : "=l"(v) : "f"(lo), "f"(hi)); return v;
}

// ---------------------------------------------------------------------------
// K_prep: blocks [0,128): coefficients (j-major, dim-pair packed, log2 domain,
//         j=0/1 importance-weight deltas folded into c).
//         blocks [128,136): per-i  log q(z|x) - log p(z).
// Also resets the last-block counter for k_main.
// ---------------------------------------------------------------------------
__global__ void k_prep(const float* __restrict__ mu, const float* __restrict__ lv,
                       const float* __restrict__ z, const int* __restrict__ nds) {
    int b = blockIdx.x;
    if (b == 0 && threadIdx.x == 0) g_count = 0u;
    if (b < 128) {
        int idx = b * 256 + threadIdx.x;          // exactly 32768 = Bsz*Dd
        int j = idx >> 4, d = idx & 15;
        float m = mu[idx], v = lv[idx];
        float a = -0.5f * LOG2E_F * ex2f(-v * LOG2E_F);
        float off = -0.5f * LOG2E_F * (v + LOG2PI_F);
        float bb = -2.0f * a * m;
        float c = fmaf(a * m, m, off);
        if (j < 2) {
            float Nf = (float)(*nds);
            float dL0 = lg2f_(2047.0f / Nf);
            float dL1 = lg2f_((Nf - 2047.0f) / Nf);
            c += (j == 0) ? dL0 : dL1;
        }
        int dp = d >> 1, h = d & 1;
        int e = j * 2 + h;
        g_pk2f[(dp * 3 + 0) * 4096 + e] = a;
        g_pk2f[(dp * 3 + 1) * 4096 + e] = bb;
        g_pk2f[(dp * 3 + 2) * 4096 + e] = c;
    } else {
        int i = (b - 128) * 256 + threadIdx.x;    // exactly 2048
        float acc = 0.f, sz2 = 0.f;
#pragma unroll
        for (int d = 0; d < Dd; d++) {
            float zd = z[i * Dd + d];
            float md = mu[i * Dd + d];
            float vd = lv[i * Dd + d];
            float t = zd - md;
            acc += -0.5f * (t * t * ex2f(-vd * LOG2E_F) + vd + LOG2PI_F);
            sz2 = fmaf(zd, zd, sz2);
        }
        float lprior = -0.5f * (sz2 * 0.36787944117144233f + 16.0f * (1.0f + LOG2PI_F));
        g_arr0[i] = acc - lprior;
    }
}

// ---------------------------------------------------------------------------
// K_main: grid = 64 recon blocks + 256 pairwise blocks, 128 threads each.
//   recon blocks  (b <  64): MAE partial sums (HBM-bound, hides under compute)
//   pairwise blocks (b >= 64): 4 warps x 2 rows = 8 rows; coefficients staged
//     into smem in 64-j double-buffered tiles; plain exp2-accumulate with
//     pre-folded weights; exact j=0/1 corrections post-loop.
// The LAST block to finish (atomic counter) does the final combine -> out[0].
// ---------------------------------------------------------------------------
__global__ void __launch_bounds__(128) k_main(const float* __restrict__ z,
                                              const int* __restrict__ nds,
                                              const float* __restrict__ x,
                                              const float* __restrict__ rec,
                                              float* __restrict__ out) {
    __shared__ float4 sbuf[2][768];               // 24 segments x 32 float4 (24 KB)
    __shared__ float sred[128];
    __shared__ unsigned s_rank;
    const int tid = threadIdx.x;
    const int lane = tid & 31;

    if (blockIdx.x < NRECON) {
        // ---------------- recon MAE partial ----------------
        float acc = 0.f;
        const float4* x4 = (const float4*)x;
        const float4* r4 = (const float4*)rec;
        const int n4 = (Bsz * Ff) / 4;
        for (int k = blockIdx.x * 128 + tid; k < n4; k += NRECON * 128) {
            float4 a = x4[k], b = r4[k];
            acc += fabsf(a.x - b.x) + fabsf(a.y - b.y) + fabsf(a.z - b.z) + fabsf(a.w - b.w);
        }
        sred[tid] = acc;
        __syncthreads();
#pragma unroll
        for (int o = 64; o > 0; o >>= 1) {
            if (tid < o) sred[tid] += sred[tid + o];
            __syncthreads();
        }
        if (tid == 0) g_part[blockIdx.x] = sred[0];
    } else {
        // ---------------- pairwise block ----------------
        const int w = tid >> 5;                           // 0..3
        const int i0 = (blockIdx.x - NRECON) * 8 + 2 * w, i1 = i0 + 1;

        ull zp0[8], zp1[8];
        {
            const float4* zq = (const float4*)(z + (size_t)i0 * Dd);
#pragma unroll
            for (int k = 0; k < 4; k++) {
                float4 v = zq[k];
                zp0[2 * k] = pk2(v.x, v.y); zp0[2 * k + 1] = pk2(v.z, v.w);
            }
            const float4* zq1 = (const float4*)(z + (size_t)i1 * Dd);
#pragma unroll
            for (int k = 0; k < 4; k++) {
                float4 v = zq1[k];
                zp1[2 * k] = pk2(v.x, v.y); zp1[2 * k + 1] = pk2(v.z, v.w);
            }
        }

        float s0[16], s1[16], srow0 = 0.f, srow1 = 0.f;
#pragma unroll
        for (int d = 0; d < 16; d++) { s0[d] = 0.f; s1[d] = 0.f; }

        const float4* gp4 = (const float4*)g_pk2f;

        // prologue: stage tile 0 (each thread 6 float4)
        {
            float4 pf[6];
#pragma unroll
            for (int k = 0; k < 6; k++) {
                int e = tid + k * 128; int s = e >> 5, q = e & 31;
                pf[k] = gp4[s * 1024 + q];
            }
#pragma unroll
            for (int k = 0; k < 6; k++) {
                int e = tid + k * 128; int s = e >> 5, q = e & 31;
                sbuf[0][s * 32 + q] = pf[k];
            }
        }
        __syncthreads();

#pragma unroll 1
        for (int t = 0; t < 32; t++) {
            float4 pf[6];
            if (t < 31) {
#pragma unroll
                for (int k = 0; k < 6; k++) {
                    int e = tid + k * 128; int s = e >> 5, q = e & 31;
                    pf[k] = gp4[s * 1024 + 32 * (t + 1) + q];
                }
            }

            const ulonglong2* sb2 = (const ulonglong2*)sbuf[t & 1];
            ull SR00 = 0ull, SR01 = 0ull, SR10 = 0ull, SR11 = 0ull;

#pragma unroll
            for (int dp = 0; dp < 8; dp++) {
                ulonglong2 A = sb2[(dp * 3 + 0) * 32 + lane];
                ulonglong2 B = sb2[(dp * 3 + 1) * 32 + lane];
                ulonglong2 C = sb2[(dp * 3 + 2) * 32 + lane];
                float l, h;
                ull u = fma2_(zp0[dp], fma2_(zp0[dp], A.x, B.x), C.x);
                unpk(u, l, h); s0[2 * dp] += ex2f(l); s0[2 * dp + 1] += ex2f(h);
                SR00 = add2_(SR00, u);
                u = fma2_(zp0[dp], fma2_(zp0[dp], A.y, B.y), C.y);
                unpk(u, l, h); s0[2 * dp] += ex2f(l); s0[2 * dp + 1] += ex2f(h);
                SR01 = add2_(SR01, u);
                u = fma2_(zp1[dp], fma2_(zp1[dp], A.x, B.x), C.x);
                unpk(u, l, h); s1[2 * dp] += ex2f(l); s1[2 * dp + 1] += ex2f(h);
                SR10 = add2_(SR10, u);
                u = fma2_(zp1[dp], fma2_(zp1[dp], A.y, B.y), C.y);
                unpk(u, l, h); s1[2 * dp] += ex2f(l); s1[2 * dp + 1] += ex2f(h);
                SR11 = add2_(SR11, u);
            }
            {
                float l, h;
                unpk(SR00, l, h); srow0 += ex2f(l + h);
                unpk(SR01, l, h); srow0 += ex2f(l + h);
                unpk(SR10, l, h); srow1 += ex2f(l + h);
                unpk(SR11, l, h); srow1 += ex2f(l + h);
            }

            if (t < 31) {
#pragma unroll
                for (int k = 0; k < 6; k++) {
                    int e = tid + k * 128; int s = e >> 5, q = e & 31;
                    sbuf[(t + 1) & 1][s * 32 + q] = pf[k];
                }
            }
            __syncthreads();
        }

        // ---- post-loop exact corrections (lane 0 owns j=0 and j=1) ----
        const ulonglong2* pk = (const ulonglong2*)g_pk2f;
        if (lane == 0) {
            float Nf = (float)(*nds);
            float dL0 = lg2f_(2047.0f / Nf);
            float dL1 = lg2f_((Nf - 2047.0f) / Nf);
            float S0_0 = 0.f, S1_0 = 0.f, S0_1 = 0.f, S1_1 = 0.f;
            float u0d0[16];
#pragma unroll
            for (int dp = 0; dp < 8; dp++) {
                ulonglong2 A = pk[(dp * 3 + 0) * 1024];
                ulonglong2 B = pk[(dp * 3 + 1) * 1024];
                ulonglong2 C = pk[(dp * 3 + 2) * 1024];
                float l, h;
                ull u0 = fma2_(zp0[dp], fma2_(zp0[dp], A.x, B.x), C.x);
                unpk(u0, l, h); S0_0 += l + h; u0d0[2 * dp] = l; u0d0[2 * dp + 1] = h;
                ull u1 = fma2_(zp0[dp], fma2_(zp0[dp], A.y, B.y), C.y);
                unpk(u1, l, h); S1_0 += l + h;
                ull v0 = fma2_(zp1[dp], fma2_(zp1[dp], A.x, B.x), C.x);
                unpk(v0, l, h); S0_1 += l + h;
                ull v1 = fma2_(zp1[dp], fma2_(zp1[dp], A.y, B.y), C.y);
                unpk(v1, l, h); S1_1 += l + h;
            }
            // row-sum: loop applied 16*dL_j; true weight is 1*dL_j(row).
            float c00 = (i0 == Bsz - 2) ? (dL1 - 16.f * dL0) : (-15.f * dL0);
            float c01 = -15.f * dL0;                  // odd rows are never B-2
            float c1  = -15.f * dL1;
            srow0 += (ex2f(c00) - 1.f) * ex2f(S0_0) + (ex2f(c1) - 1.f) * ex2f(S1_0);
            srow1 += (ex2f(c01) - 1.f) * ex2f(S0_1) + (ex2f(c1) - 1.f) * ex2f(S1_1);
            // W[B-2, 0] per-dim override (row B-2 is even -> row i0)
            if (i0 == Bsz - 2) {
                float wfix = ex2f(dL1 - dL0) - 1.f;
#pragma unroll
                for (int d = 0; d < 16; d++) s0[d] += wfix * ex2f(u0d0[d]);
            }
        }

        // ---- plain-sum butterfly ----
#pragma unroll
        for (int off = 16; off > 0; off >>= 1) {
#pragma unroll
            for (int d = 0; d < 16; d++) {
                s0[d] += __shfl_xor_sync(0xffffffffu, s0[d], off);
                s1[d] += __shfl_xor_sync(0xffffffffu, s1[d], off);
            }
            srow0 += __shfl_xor_sync(0xffffffffu, srow0, off);
            srow1 += __shfl_xor_sync(0xffffffffu, srow1, off);
        }

        if (lane == 0) {
            g_lqz[i0] = lg2f_(srow0);
            g_lqz[i1] = lg2f_(srow1);
            float p0 = 0.f, p1 = 0.f;
#pragma unroll
            for (int d = 0; d < 16; d++) { p0 += lg2f_(s0[d]); p1 += lg2f_(s1[d]); }
            g_lqzp[i0] = p0;
            g_lqzp[i1] = p1;
        }
    }

    // ---------------- last-block final combine ----------------
    __threadfence();
    __syncthreads();
    if (tid == 0) s_rank = atomicAdd(&g_count, 1u);
    __syncthreads();
    if (s_rank == NGRID - 1) {
        // total = recon_mean + mean(arr0) + 3*ln2*mean(lg2srow - sum_lg2s)
        //         + 45*ln(2047)   (the -15*Lc row-weight constant, x3)
        float c = 0.f;
        for (int k = tid; k < Bsz; k += 128)
            c += g_arr0[k] + 3.f * LN2_F * (g_lqz[k] - g_lqzp[k]);
        float rp = (tid < NRECON) ? g_part[tid] : 0.f;

        sred[tid] = c;
        __syncthreads();
#pragma unroll
        for (int o = 64; o > 0; o >>= 1) {
            if (tid < o) sred[tid] += sred[tid + o];
            __syncthreads();
        }
        float ctot = sred[0];
        __syncthreads();
        sred[tid] = rp;
        __syncthreads();
#pragma unroll
        for (int o = 64; o > 0; o >>= 1) {
            if (tid < o) sred[tid] += sred[tid + o];
            __syncthreads();
        }
        if (tid == 0)
            out[0] = sred[0] / (float)(Bsz * Ff) + ctot / (float)Bsz
                   + 45.0f * logf(2047.0f);
    }
}

extern "C" void kernel_launch(void* const* d_in, const int* in_sizes, int n_in,
                              void* d_out, int out_size) {
    const float* x   = (const float*)d_in[0];
    const float* rec = (const float*)d_in[1];
    const float* mu  = (const float*)d_in[2];
    const float* lv  = (const float*)d_in[3];
    const float* z   = (const float*)d_in[4];
    const int*   nds = (const int*)d_in[5];
    float* out = (float*)d_out;

    k_prep<<<136, 256>>>(mu, lv, z, nds);
    k_main<<<NGRID, 128>>>(z, nds, x, rec, out);
}

// round 9
// speedup vs baseline: 1.8027x; 1.8027x over previous
#include <cuda_runtime.h>
#include <math_constants.h>

#define Bsz 2048
#define Dd 16
#define Ff 512
#define LOG2E_F 1.4426950408889634f
#define LN2_F 0.6931471805599453f
#define LOG2PI_F 1.8378770664093453f

#define NPAIR 128            // pairwise blocks (16 rows each), scheduled FIRST
#define NRECON 64            // recon blocks fill idle SMs / trailing wave
#define NGRID (NPAIR + NRECON)

typedef unsigned long long ull;

// Coefficient store: segment s = dp*3 + type (dp=dim-pair 0..7, type a/b/c),
// each segment is float2[2048] over j: float2[j] = {coef_{2dp}[j], coef_{2dp+1}[j]}
__device__ float g_pk2f[24 * 2048 * 2];   // 393 KB
__device__ float g_arr0[Bsz];             // log q(z|x) - log p(z)
__device__ float g_comb[Bsz];             // arr0 + 3*ln2*(lg2 srow - sum lg2 s_d)
__device__ float g_part[NRECON];          // recon partials
__device__ unsigned g_count;              // last-block-done counter

__device__ __forceinline__ float ex2f(float x) {
    float y; asm("ex2.approx.ftz.f32 %0, %1;" : "=f"(y) : "f"(x)); return y;
}
__device__ __forceinline__ float lg2f_(float x) {
    float y; asm("lg2.approx.f32 %0, %1;" : "=f"(y) : "f"(x)); return y;
}
__device__ __forceinline__ ull fma2_(ull a, ull b, ull c) {
    ull d; asm("fma.rn.f32x2 %0, %1, %2, %3;" : "=l"(d) : "l"(a), "l"(b), "l"(c)); return d;
}
__device__ __forceinline__ ull add2_(ull a, ull b) {
    ull d; asm("add.rn.f32x2 %0, %1, %2;" : "=l"(d) : "l"(a), "l"(b)); return d;
}
__device__ __forceinline__ void unpk(ull v, float& lo, float& hi) {
    asm("mov.b64 {%0, %1}, %2;" : "=f"(lo), "=f"(hi) : "l"(v));
}
__device__ __forceinline__ ull pk2(float lo, float hi) {
    ull v; asm("mov.b64 %0, {%1, %2};" : "=l"(v) : "f"(lo), "f"(hi)); return v;
}

// ---------------------------------------------------------------------------
// K_prep: blocks [0,128): coefficients (j-major, dim-pair packed, log2 domain,
//         j=0/1 importance-weight deltas folded into c).
//         blocks [128,136): per-i  log q(z|x) - log p(z).
// Also resets the last-block counter for k_main.
// ---------------------------------------------------------------------------
__global__ void k_prep(const float* __restrict__ mu, const float* __restrict__ lv,
                       const float* __restrict__ z, const int* __restrict__ nds) {
    int b = blockIdx.x;
    if (b == 0 && threadIdx.x == 0) g_count = 0u;
    if (b < 128) {
        int idx = b * 256 + threadIdx.x;          // exactly 32768 = Bsz*Dd
        int j = idx >> 4, d = idx & 15;
        float m = mu[idx], v = lv[idx];
        float a = -0.5f * LOG2E_F * ex2f(-v * LOG2E_F);
        float off = -0.5f * LOG2E_F * (v + LOG2PI_F);
        float bb = -2.0f * a * m;
        float c = fmaf(a * m, m, off);
        if (j < 2) {
            float Nf = (float)(*nds);
            float dL0 = lg2f_(2047.0f / Nf);
            float dL1 = lg2f_((Nf - 2047.0f) / Nf);
            c += (j == 0) ? dL0 : dL1;
        }
        int dp = d >> 1, h = d & 1;
        int e = j * 2 + h;
        g_pk2f[(dp * 3 + 0) * 4096 + e] = a;
        g_pk2f[(dp * 3 + 1) * 4096 + e] = bb;
        g_pk2f[(dp * 3 + 2) * 4096 + e] = c;
    } else {
        int i = (b - 128) * 256 + threadIdx.x;    // exactly 2048
        float acc = 0.f, sz2 = 0.f;
#pragma unroll
        for (int d = 0; d < Dd; d++) {
            float zd = z[i * Dd + d];
            float md = mu[i * Dd + d];
            float vd = lv[i * Dd + d];
            float t = zd - md;
            acc += -0.5f * (t * t * ex2f(-vd * LOG2E_F) + vd + LOG2PI_F);
            sz2 = fmaf(zd, zd, sz2);
        }
        float lprior = -0.5f * (sz2 * 0.36787944117144233f + 16.0f * (1.0f + LOG2PI_F));
        g_arr0[i] = acc - lprior;
    }
}

// ---------------------------------------------------------------------------
// K_main: grid = 128 pairwise blocks (first) + 64 recon blocks, 256 threads.
//   Pairwise (b < 128): 8 warps x 2 rows = 16 rows; coefficients staged into
//     smem in 64-j double-buffered tiles (3 float4 per thread per tile);
//     plain exp2-accumulate with pre-folded weights; exact j=0/1 corrections
//     post-loop; per-row combine written to g_comb.
//   Recon (b >= 128): MAE partial sums on otherwise-idle SMs.
// LAST block to finish (atomic counter, fixed-order reduce) writes out[0].
// ---------------------------------------------------------------------------
__global__ void __launch_bounds__(256) k_main(const float* __restrict__ z,
                                              const int* __restrict__ nds,
                                              const float* __restrict__ x,
                                              const float* __restrict__ rec,
                                              float* __restrict__ out) {
    __shared__ float4 sbuf[2][768];               // 24 segments x 32 float4 (24 KB)
    __shared__ float sred[256];
    __shared__ unsigned s_rank;
    const int tid = threadIdx.x;
    const int lane = tid & 31;

    if (blockIdx.x < NPAIR) {
        // ---------------- pairwise block ----------------
        const int w = tid >> 5;                           // 0..7
        const int i0 = blockIdx.x * 16 + 2 * w, i1 = i0 + 1;

        ull zp0[8], zp1[8];
        {
            const float4* zq = (const float4*)(z + (size_t)i0 * Dd);
#pragma unroll
            for (int k = 0; k < 4; k++) {
                float4 v = zq[k];
                zp0[2 * k] = pk2(v.x, v.y); zp0[2 * k + 1] = pk2(v.z, v.w);
            }
            const float4* zq1 = (const float4*)(z + (size_t)i1 * Dd);
#pragma unroll
            for (int k = 0; k < 4; k++) {
                float4 v = zq1[k];
                zp1[2 * k] = pk2(v.x, v.y); zp1[2 * k + 1] = pk2(v.z, v.w);
            }
        }

        float s0[16], s1[16], srow0 = 0.f, srow1 = 0.f;
#pragma unroll
        for (int d = 0; d < 16; d++) { s0[d] = 0.f; s1[d] = 0.f; }

        const float4* gp4 = (const float4*)g_pk2f;

        // prologue: stage tile 0 (each thread 3 float4)
        {
            float4 pf[3];
#pragma unroll
            for (int k = 0; k < 3; k++) {
                int e = tid + k * 256; int s = e >> 5, q = e & 31;
                pf[k] = gp4[s * 1024 + q];
            }
#pragma unroll
            for (int k = 0; k < 3; k++) {
                int e = tid + k * 256; int s = e >> 5, q = e & 31;
                sbuf[0][s * 32 + q] = pf[k];
            }
        }
        __syncthreads();

#pragma unroll 1
        for (int t = 0; t < 32; t++) {
            float4 pf[3];
            if (t < 31) {
#pragma unroll
                for (int k = 0; k < 3; k++) {
                    int e = tid + k * 256; int s = e >> 5, q = e & 31;
                    pf[k] = gp4[s * 1024 + 32 * (t + 1) + q];
                }
            }

            const ulonglong2* sb2 = (const ulonglong2*)sbuf[t & 1];
            ull SR00 = 0ull, SR01 = 0ull, SR10 = 0ull, SR11 = 0ull;

#pragma unroll
            for (int dp = 0; dp < 8; dp++) {
                ulonglong2 A = sb2[(dp * 3 + 0) * 32 + lane];
                ulonglong2 B = sb2[(dp * 3 + 1) * 32 + lane];
                ulonglong2 C = sb2[(dp * 3 + 2) * 32 + lane];
                float l, h;
                ull u = fma2_(zp0[dp], fma2_(zp0[dp], A.x, B.x), C.x);
                unpk(u, l, h); s0[2 * dp] += ex2f(l); s0[2 * dp + 1] += ex2f(h);
                SR00 = add2_(SR00, u);
                u = fma2_(zp0[dp], fma2_(zp0[dp], A.y, B.y), C.y);
                unpk(u, l, h); s0[2 * dp] += ex2f(l); s0[2 * dp + 1] += ex2f(h);
                SR01 = add2_(SR01, u);
                u = fma2_(zp1[dp], fma2_(zp1[dp], A.x, B.x), C.x);
                unpk(u, l, h); s1[2 * dp] += ex2f(l); s1[2 * dp + 1] += ex2f(h);
                SR10 = add2_(SR10, u);
                u = fma2_(zp1[dp], fma2_(zp1[dp], A.y, B.y), C.y);
                unpk(u, l, h); s1[2 * dp] += ex2f(l); s1[2 * dp + 1] += ex2f(h);
                SR11 = add2_(SR11, u);
            }
            {
                float l, h;
                unpk(SR00, l, h); srow0 += ex2f(l + h);
                unpk(SR01, l, h); srow0 += ex2f(l + h);
                unpk(SR10, l, h); srow1 += ex2f(l + h);
                unpk(SR11, l, h); srow1 += ex2f(l + h);
            }

            if (t < 31) {
#pragma unroll
                for (int k = 0; k < 3; k++) {
                    int e = tid + k * 256; int s = e >> 5, q = e & 31;
                    sbuf[(t + 1) & 1][s * 32 + q] = pf[k];
                }
            }
            __syncthreads();
        }

        // ---- post-loop exact corrections (lane 0 owns j=0 and j=1) ----
        const ulonglong2* pk = (const ulonglong2*)g_pk2f;
        if (lane == 0) {
            float Nf = (float)(*nds);
            float dL0 = lg2f_(2047.0f / Nf);
            float dL1 = lg2f_((Nf - 2047.0f) / Nf);
            float S0_0 = 0.f, S1_0 = 0.f, S0_1 = 0.f, S1_1 = 0.f;
            float u0d0[16];
#pragma unroll
            for (int dp = 0; dp < 8; dp++) {
                ulonglong2 A = pk[(dp * 3 + 0) * 1024];
                ulonglong2 B = pk[(dp * 3 + 1) * 1024];
                ulonglong2 C = pk[(dp * 3 + 2) * 1024];
                float l, h;
                ull u0 = fma2_(zp0[dp], fma2_(zp0[dp], A.x, B.x), C.x);
                unpk(u0, l, h); S0_0 += l + h; u0d0[2 * dp] = l; u0d0[2 * dp + 1] = h;
                ull u1 = fma2_(zp0[dp], fma2_(zp0[dp], A.y, B.y), C.y);
                unpk(u1, l, h); S1_0 += l + h;
                ull v0 = fma2_(zp1[dp], fma2_(zp1[dp], A.x, B.x), C.x);
                unpk(v0, l, h); S0_1 += l + h;
                ull v1 = fma2_(zp1[dp], fma2_(zp1[dp], A.y, B.y), C.y);
                unpk(v1, l, h); S1_1 += l + h;
            }
            // row-sum: loop applied 16*dL_j; true weight is 1*dL_j(row).
            float c00 = (i0 == Bsz - 2) ? (dL1 - 16.f * dL0) : (-15.f * dL0);
            float c01 = -15.f * dL0;                  // odd rows are never B-2
            float c1  = -15.f * dL1;
            srow0 += (ex2f(c00) - 1.f) * ex2f(S0_0) + (ex2f(c1) - 1.f) * ex2f(S1_0);
            srow1 += (ex2f(c01) - 1.f) * ex2f(S0_1) + (ex2f(c1) - 1.f) * ex2f(S1_1);
            // W[B-2, 0] per-dim override (row B-2 is even -> row i0)
            if (i0 == Bsz - 2) {
                float wfix = ex2f(dL1 - dL0) - 1.f;
#pragma unroll
                for (int d = 0; d < 16; d++) s0[d] += wfix * ex2f(u0d0[d]);
            }
        }

        // ---- plain-sum butterfly ----
#pragma unroll
        for (int off = 16; off > 0; off >>= 1) {
#pragma unroll
            for (int d = 0; d < 16; d++) {
                s0[d] += __shfl_xor_sync(0xffffffffu, s0[d], off);
                s1[d] += __shfl_xor_sync(0xffffffffu, s1[d], off);
            }
            srow0 += __shfl_xor_sync(0xffffffffu, srow0, off);
            srow1 += __shfl_xor_sync(0xffffffffu, srow1, off);
        }

        if (lane == 0) {
            float p0 = 0.f, p1 = 0.f;
#pragma unroll
            for (int d = 0; d < 16; d++) { p0 += lg2f_(s0[d]); p1 += lg2f_(s1[d]); }
            g_comb[i0] = g_arr0[i0] + 3.f * LN2_F * (lg2f_(srow0) - p0);
            g_comb[i1] = g_arr0[i1] + 3.f * LN2_F * (lg2f_(srow1) - p1);
        }
    } else {
        // ---------------- recon MAE partial ----------------
        const int rb = blockIdx.x - NPAIR;
        float acc = 0.f;
        const float4* x4 = (const float4*)x;
        const float4* r4 = (const float4*)rec;
        const int n4 = (Bsz * Ff) / 4;
        for (int k = rb * 256 + tid; k < n4; k += NRECON * 256) {
            float4 a = x4[k], b = r4[k];
            acc += fabsf(a.x - b.x) + fabsf(a.y - b.y) + fabsf(a.z - b.z) + fabsf(a.w - b.w);
        }
        sred[tid] = acc;
        __syncthreads();
#pragma unroll
        for (int o = 128; o > 0; o >>= 1) {
            if (tid < o) sred[tid] += sred[tid + o];
            __syncthreads();
        }
        if (tid == 0) g_part[rb] = sred[0];
    }

    // ---------------- last-block final combine ----------------
    __threadfence();
    __syncthreads();
    if (tid == 0) s_rank = atomicAdd(&g_count, 1u);
    __syncthreads();
    if (s_rank == NGRID - 1) {
        // total = recon_mean + mean(comb) + 45*ln(2047)
        float c = 0.f;
#pragma unroll
        for (int k = 0; k < Bsz / 256; k++)
            c += g_comb[tid + k * 256];
        float rp = (tid < NRECON) ? g_part[tid] : 0.f;

        sred[tid] = c;
        __syncthreads();
#pragma unroll
        for (int o = 128; o > 0; o >>= 1) {
            if (tid < o) sred[tid] += sred[tid + o];
            __syncthreads();
        }
        float ctot = sred[0];
        __syncthreads();
        sred[tid] = rp;
        __syncthreads();
#pragma unroll
        for (int o = 128; o > 0; o >>= 1) {
            if (tid < o) sred[tid] += sred[tid + o];
            __syncthreads();
        }
        if (tid == 0)
            out[0] = sred[0] / (float)(Bsz * Ff) + ctot / (float)Bsz
                   + 45.0f * logf(2047.0f);
    }
}

extern "C" void kernel_launch(void* const* d_in, const int* in_sizes, int n_in,
                              void* d_out, int out_size) {
    const float* x   = (const float*)d_in[0];
    const float* rec = (const float*)d_in[1];
    const float* mu  = (const float*)d_in[2];
    const float* lv  = (const float*)d_in[3];
    const float* z   = (const float*)d_in[4];
    const int*   nds = (const int*)d_in[5];
    float* out = (float*)d_out;

    k_prep<<<136, 256>>>(mu, lv, z, nds);
    k_main<<<NGRID, 256>>>(z, nds, x, rec, out);
}